// round 13
// baseline (speedup 1.0000x reference)
#include <cuda_runtime.h>
#include <cstdint>

// ============================================================================
// QuantizedLinear: out = clip(round(fma((x_q-128)@W^T, 2e-4, bias)), 0..255)
// M=4096, K=4096, N=11008.
// ROUND 13: the round-12 contract dump proved the INPUT model was right all
// along. The only surviving explanation for bit-exact rel_err=1.000000 across
// 10 kernels is that d_out's __output__ dtype is FLOAT32: int32 stores read
// back as denormals (~1e-43) -> ||out||~0 -> rel_err exactly 1.0.
// Single change: write the quantized result as float32.
// Engine: audited dp4a GEMM (rounds 8-10), FMA epilogue.
// ============================================================================

#define MDIM 4096
#define KDIM 4096
#define NDIM 11008

#define X_ZP 128
#define SXW_SCALE (0.02f * 0.01f)     // compile-time RN f32 == jnp f32 multiply

#define BM 128
#define BN 128
#define BK 64                         // k-elements (bytes) per stage
#define BKW (BK / 4)                  // 16 u32 k-chunks per stage
#define KTILES (KDIM / BK)            // 64
#define APITCH (BM + 4)               // u32 pitch; 132*4 bytes, 16B-divisible

__device__ __forceinline__ uint32_t qk_pack4(const int* p, int zp) {
    return  ((uint32_t)(uint8_t)(p[0] - zp))
          | (((uint32_t)(uint8_t)(p[1] - zp)) << 8)
          | (((uint32_t)(uint8_t)(p[2] - zp)) << 16)
          | (((uint32_t)(uint8_t)(p[3] - zp)) << 24);
}

__global__ void __launch_bounds__(256) qk_dp4a_gemm(
    float* __restrict__ out,          // FLOAT32 output (the round-13 change)
    const int* __restrict__ xq,       // [M,K] int32 (quint8 values, zp=128)
    const int* __restrict__ wq,       // [N,K] int32 (qint8 values)
    const float* __restrict__ bias)   // [N] f32
{
    __shared__ uint32_t smA[2][BKW][APITCH];
    __shared__ uint32_t smB[2][BKW][APITCH];

    const int tid = threadIdx.x;
    const int tx = tid & 15;          // 8-col n group
    const int ty = tid >> 4;          // 8-row m group

    const int n0 = blockIdx.x * BN;   // n fastest
    const int m0 = blockIdx.y * BM;

    int acc[8][8];
#pragma unroll
    for (int i = 0; i < 8; i++)
#pragma unroll
        for (int j = 0; j < 8; j++) acc[i][j] = 0;

    uint32_t stA[2][4], stB[2][4];
    int rA[2], cA[2];

    auto load_regs = [&](int kt) {
#pragma unroll
        for (int t = 0; t < 2; t++) {
            const int c = tid + t * 256;
            const int row = c >> 2, c16 = c & 3;
            rA[t] = row; cA[t] = c16;
            const int* pa = xq + (size_t)(m0 + row) * KDIM + kt * BK + c16 * 16;
            const int* pb = wq + (size_t)(n0 + row) * KDIM + kt * BK + c16 * 16;
#pragma unroll
            for (int j = 0; j < 4; j++) {
                stA[t][j] = qk_pack4(pa + 4 * j, X_ZP);
                stB[t][j] = qk_pack4(pb + 4 * j, 0);
            }
        }
    };

    auto store_smem = [&](int buf) {
#pragma unroll
        for (int t = 0; t < 2; t++) {
#pragma unroll
            for (int j = 0; j < 4; j++) {
                smA[buf][cA[t] * 4 + j][rA[t]] = stA[t][j];
                smB[buf][cA[t] * 4 + j][rA[t]] = stB[t][j];
            }
        }
    };

    auto compute = [&](int buf) {
#pragma unroll
        for (int kc = 0; kc < BKW; kc++) {
            uint4 a03 = *(const uint4*)&smA[buf][kc][ty * 8];
            uint4 a47 = *(const uint4*)&smA[buf][kc][ty * 8 + 4];
            uint4 b03 = *(const uint4*)&smB[buf][kc][tx * 8];
            uint4 b47 = *(const uint4*)&smB[buf][kc][tx * 8 + 4];
            const uint32_t av[8] = {a03.x, a03.y, a03.z, a03.w,
                                    a47.x, a47.y, a47.z, a47.w};
            const uint32_t bv[8] = {b03.x, b03.y, b03.z, b03.w,
                                    b47.x, b47.y, b47.z, b47.w};
#pragma unroll
            for (int i = 0; i < 8; i++)
#pragma unroll
                for (int j = 0; j < 8; j++)
                    acc[i][j] = __dp4a((int)av[i], (int)bv[j], acc[i][j]);
        }
    };

    load_regs(0);
    store_smem(0);
    __syncthreads();

    for (int kt = 0; kt < KTILES; kt++) {
        if (kt + 1 < KTILES) load_regs(kt + 1);
        compute(kt & 1);
        if (kt + 1 < KTILES) store_smem((kt + 1) & 1);
        __syncthreads();
    }

    // ---- epilogue: dequant + bias + requant; STORE AS FLOAT32 ----
    const float sxw = SXW_SCALE;
#pragma unroll
    for (int i = 0; i < 8; i++) {
        const long row = m0 + ty * 8 + i;
        float* orow = out + row * (long)NDIM + n0 + tx * 8;
#pragma unroll
        for (int jv = 0; jv < 2; jv++) {
            float4 v;
#pragma unroll
            for (int e = 0; e < 4; e++) {
                const int j = jv * 4 + e;
                const float b = bias[n0 + tx * 8 + j];
                float y = __fmaf_rn((float)acc[i][j], sxw, b);
                float q = rintf(y);
                q = fminf(fmaxf(q, 0.0f), 255.0f);
                ((float*)&v)[e] = q;
            }
            *(float4*)(orow + jv * 4) = v;
        }
    }
}

// --------------------------------------------------------------------- launch
extern "C" void kernel_launch(void* const* d_in, const int* in_sizes, int n_in,
                              void* d_out, int out_size) {
    (void)in_sizes; (void)n_in; (void)out_size;

    // Contract verified in round 12: positional order matches the reference.
    const int*   xq   = (const int*)d_in[0];   // 16777216 int32
    const int*   wq   = (const int*)d_in[1];   // 45088768 int32
    const float* bias = (const float*)d_in[2]; // 11008 f32

    dim3 grid(NDIM / BN, MDIM / BM);   // (86, 32)
    qk_dp4a_gemm<<<grid, 256>>>((float*)d_out, xq, wq, bias);
}

// round 14
// speedup vs baseline: 2.6970x; 2.6970x over previous
#include <cuda_runtime.h>
#include <cstdint>

// ============================================================================
// QuantizedLinear: out_f32 = clip(round(fma((x_q-128)@W^T, 2e-4, bias)),0..255)
// M=4096, K=4096, N=11008.
// ROUND 14: reinstate the IMMA tensor engine (rounds 2-5 — correct all along;
// they failed only on output dtype) with the float32 epilogue that passed.
// int8 prepass -> cp.async 3-stage -> ldmatrix -> mma.sync m16n8k32 s8.
// ============================================================================

#define MDIM 4096
#define KDIM 4096
#define NDIM 11008

#define X_ZP 128
#define SXW_SCALE (0.02f * 0.01f)

#define BM 128
#define BN 128
#define BK 64
#define NST 3
#define KTILES (KDIM / BK)               // 64

#define A_STAGE_BYTES (BM * BK)          // 8192
#define B_STAGE_BYTES (BN * BK)          // 8192
#define STAGE_BYTES (A_STAGE_BYTES + B_STAGE_BYTES)   // 16384
#define SMEM_TOTAL (NST * STAGE_BYTES)   // 49152 = static-smem limit

// int8 scratch (allocation-free __device__ globals, symbol-addressed)
__device__ __align__(256) int8_t g_qk_A[(size_t)MDIM * KDIM];  // (x_q-128) s8
__device__ __align__(256) int8_t g_qk_B[(size_t)NDIM * KDIM];  // w_q s8

// ---------------------------------------------------------------- PTX helpers
__device__ __forceinline__ uint32_t qk_smem_u32(const void* p) {
    uint32_t a;
    asm("{ .reg .u64 t; cvta.to.shared.u64 t, %1; cvt.u32.u64 %0, t; }"
        : "=r"(a) : "l"(p));
    return a;
}
__device__ __forceinline__ void qk_cp_async16(uint32_t dst, const void* src) {
    asm volatile("cp.async.cg.shared.global [%0], [%1], 16;"
                 :: "r"(dst), "l"(src) : "memory");
}
__device__ __forceinline__ void qk_cp_commit() {
    asm volatile("cp.async.commit_group;" ::: "memory");
}
__device__ __forceinline__ void qk_cp_wait() {
    asm volatile("cp.async.wait_group 1;" ::: "memory");   // NST-2
}
__device__ __forceinline__ void qk_ldsm_x4(uint32_t& r0, uint32_t& r1,
                                           uint32_t& r2, uint32_t& r3,
                                           uint32_t addr) {
    asm volatile("ldmatrix.sync.aligned.m8n8.x4.shared.b16 {%0,%1,%2,%3}, [%4];"
                 : "=r"(r0), "=r"(r1), "=r"(r2), "=r"(r3) : "r"(addr));
}
__device__ __forceinline__ void qk_mma_s8(int* c, const uint32_t* a,
                                          uint32_t b0, uint32_t b1) {
    asm volatile(
        "mma.sync.aligned.m16n8k32.row.col.s32.s8.s8.s32 "
        "{%0,%1,%2,%3}, {%4,%5,%6,%7}, {%8,%9}, {%0,%1,%2,%3};"
        : "+r"(c[0]), "+r"(c[1]), "+r"(c[2]), "+r"(c[3])
        : "r"(a[0]), "r"(a[1]), "r"(a[2]), "r"(a[3]), "r"(b0), "r"(b1));
}
// swizzle: (row>>1)&3 XOR on 16B columns — conflict-free ldmatrix fetches
__device__ __forceinline__ uint32_t qk_sw(int row, int c16) {
    return (uint32_t)(row * 64 + ((c16 ^ ((row >> 1) & 3)) << 4));
}

// ------------------------------------------------------------ prepass kernels
__global__ void qk_cvt_a(const int* __restrict__ in, int n4) {
    int i = blockIdx.x * blockDim.x + threadIdx.x;
    if (i >= n4) return;
    const int v0 = in[4 * i + 0] - X_ZP;
    const int v1 = in[4 * i + 1] - X_ZP;
    const int v2 = in[4 * i + 2] - X_ZP;
    const int v3 = in[4 * i + 3] - X_ZP;
    ((uint32_t*)g_qk_A)[i] =
          ((uint32_t)(uint8_t)v0)        | (((uint32_t)(uint8_t)v1) << 8)
        | (((uint32_t)(uint8_t)v2) << 16) | (((uint32_t)(uint8_t)v3) << 24);
}
__global__ void qk_cvt_b(const int* __restrict__ in, int n4) {
    int i = blockIdx.x * blockDim.x + threadIdx.x;
    if (i >= n4) return;
    const int v0 = in[4 * i + 0];
    const int v1 = in[4 * i + 1];
    const int v2 = in[4 * i + 2];
    const int v3 = in[4 * i + 3];
    ((uint32_t*)g_qk_B)[i] =
          ((uint32_t)(uint8_t)v0)        | (((uint32_t)(uint8_t)v1) << 8)
        | (((uint32_t)(uint8_t)v2) << 16) | (((uint32_t)(uint8_t)v3) << 24);
}

// ---------------------------------------------------------------- GEMM kernel
__device__ __forceinline__ void qk_load_stage(uint32_t sbase, int m0, int n0,
                                              int kt, int tid) {
#pragma unroll
    for (int t = 0; t < 2; t++) {
        const int chunk = tid + t * 256;
        const int row = chunk >> 2, c16 = chunk & 3;
        qk_cp_async16(sbase + qk_sw(row, c16),
                      g_qk_A + (size_t)(m0 + row) * KDIM + kt * BK + c16 * 16);
    }
#pragma unroll
    for (int t = 0; t < 2; t++) {
        const int chunk = tid + t * 256;
        const int row = chunk >> 2, c16 = chunk & 3;
        qk_cp_async16(sbase + A_STAGE_BYTES + qk_sw(row, c16),
                      g_qk_B + (size_t)(n0 + row) * KDIM + kt * BK + c16 * 16);
    }
}

__global__ void __launch_bounds__(256) qk_gemm_i8(
    float* __restrict__ out, const float* __restrict__ bias)
{
    __shared__ __align__(1024) int8_t smem[SMEM_TOTAL];
    const uint32_t sb = qk_smem_u32(smem);
    const int tid = threadIdx.x;
    const int wid = tid >> 5;
    const int lid = tid & 31;
    const int wm = wid >> 2;          // 0..1 : 64-row M chunk
    const int wn = wid & 3;           // 0..3 : 32-col N chunk

    const int n0 = blockIdx.x * BN;   // n fastest: B s8 slab (45MB) L2-resident
    const int m0 = blockIdx.y * BM;

    int acc[4][4][4];
#pragma unroll
    for (int i = 0; i < 4; i++)
#pragma unroll
        for (int j = 0; j < 4; j++)
#pragma unroll
            for (int e = 0; e < 4; e++) acc[i][j][e] = 0;

#pragma unroll
    for (int s = 0; s < NST - 1; s++) {
        qk_load_stage(sb + s * STAGE_BYTES, m0, n0, s, tid);
        qk_cp_commit();
    }

    const int lrow = lid & 15;
    const int lc   = lid >> 4;

    for (int kt = 0; kt < KTILES; kt++) {
        const int sc = kt % NST;
        qk_cp_wait();
        __syncthreads();

        const int ktp = kt + NST - 1;
        if (ktp < KTILES)
            qk_load_stage(sb + (ktp % NST) * STAGE_BYTES, m0, n0, ktp, tid);
        qk_cp_commit();

        const uint32_t sA = sb + sc * STAGE_BYTES;
        const uint32_t sBB = sA + A_STAGE_BYTES;

#pragma unroll
        for (int kk = 0; kk < 2; kk++) {
            const int c16 = kk * 2 + lc;
            uint32_t a[4][4];
#pragma unroll
            for (int mf = 0; mf < 4; mf++) {
                const int row = wm * 64 + mf * 16 + lrow;
                qk_ldsm_x4(a[mf][0], a[mf][1], a[mf][2], a[mf][3],
                           sA + qk_sw(row, c16));
            }
            uint32_t bq[2][4];
#pragma unroll
            for (int bh = 0; bh < 2; bh++) {
                const int row = wn * 32 + bh * 16 + lrow;
                qk_ldsm_x4(bq[bh][0], bq[bh][1], bq[bh][2], bq[bh][3],
                           sBB + qk_sw(row, c16));
            }
#pragma unroll
            for (int mf = 0; mf < 4; mf++)
#pragma unroll
                for (int nf = 0; nf < 4; nf++) {
                    const int bh = nf >> 1, pr = nf & 1;
                    qk_mma_s8(acc[mf][nf], a[mf], bq[bh][pr], bq[bh][pr + 2]);
                }
        }
        __syncthreads();
    }

    // -------- epilogue: dequant + bias + requant; FLOAT32 output --------
    const float sxw = SXW_SCALE;
    const int qrow = lid >> 2;        // 0..7
    const int qcol = (lid & 3) * 2;   // 0,2,4,6

#pragma unroll
    for (int nf = 0; nf < 4; nf++) {
        const int col = n0 + wn * 32 + nf * 8 + qcol;
        const float b0 = bias[col];
        const float b1 = bias[col + 1];
#pragma unroll
        for (int mf = 0; mf < 4; mf++) {
            const int r0 = m0 + wm * 64 + mf * 16 + qrow;
#pragma unroll
            for (int h = 0; h < 2; h++) {
                const long row = r0 + h * 8;
                float y0 = __fmaf_rn((float)acc[mf][nf][2 * h + 0], sxw, b0);
                float y1 = __fmaf_rn((float)acc[mf][nf][2 * h + 1], sxw, b1);
                float q0 = fminf(fmaxf(rintf(y0), 0.0f), 255.0f);
                float q1 = fminf(fmaxf(rintf(y1), 0.0f), 255.0f);
                float2 v = make_float2(q0, q1);
                *(float2*)(out + row * (long)NDIM + col) = v;
            }
        }
    }
}

// --------------------------------------------------------------------- launch
extern "C" void kernel_launch(void* const* d_in, const int* in_sizes, int n_in,
                              void* d_out, int out_size) {
    (void)in_sizes; (void)n_in; (void)out_size;

    const int*   xq   = (const int*)d_in[0];
    const int*   wq   = (const int*)d_in[1];
    const float* bias = (const float*)d_in[2];

    const int nx4 = (MDIM * KDIM) / 4;
    const int nw4 = (NDIM * KDIM) / 4;
    qk_cvt_a<<<(nx4 + 255) / 256, 256>>>(xq, nx4);
    qk_cvt_b<<<(nw4 + 255) / 256, 256>>>(wq, nw4);

    dim3 grid(NDIM / BN, MDIM / BM);   // (86, 32)
    qk_gemm_i8<<<grid, 256>>>((float*)d_out, bias);
}

// round 15
// speedup vs baseline: 2.7459x; 1.0182x over previous
#include <cuda_runtime.h>
#include <cstdint>

// ============================================================================
// QuantizedLinear: out_f32 = clip(round(fma((x_q-128)@W^T, 2e-4, bias)),0..255)
// M=4096, K=4096, N=11008.
// ROUND 15: kill the LDGSTS issue bottleneck (180M ops x 8cyc ~= 2.4M cyc).
// Prepass writes K-tiled, PRE-SWIZZLED int8 scratch; the GEMM stages each
// 8KB tile with ONE cp.async.bulk (mbarrier complete_tx) instead of 512
// per-thread cp.async. Mainloop (ldmatrix + IMMA m16n8k32) unchanged.
// ============================================================================

#define MDIM 4096
#define KDIM 4096
#define NDIM 11008

#define X_ZP 128
#define SXW_SCALE (0.02f * 0.01f)

#define BM 128
#define BN 128
#define BK 64
#define NST 3
#define KTILES (KDIM / BK)               // 64

#define A_STAGE_BYTES (BM * BK)          // 8192
#define B_STAGE_BYTES (BN * BK)          // 8192
#define STAGE_BYTES (A_STAGE_BYTES + B_STAGE_BYTES)   // 16384
#define SMEM_TOTAL (NST * STAGE_BYTES)   // 49152

// K-tiled, pre-swizzled int8 scratch: [kt][row][64B-with-chunk-swizzle]
__device__ __align__(256) int8_t g_qk_At[(size_t)MDIM * KDIM];
__device__ __align__(256) int8_t g_qk_Bt[(size_t)NDIM * KDIM];

// ---------------------------------------------------------------- PTX helpers
__device__ __forceinline__ uint32_t qk_smem_u32(const void* p) {
    uint32_t a;
    asm("{ .reg .u64 t; cvta.to.shared.u64 t, %1; cvt.u32.u64 %0, t; }"
        : "=r"(a) : "l"(p));
    return a;
}
__device__ __forceinline__ void qk_mbar_init(uint32_t mb, uint32_t cnt) {
    asm volatile("mbarrier.init.shared.b64 [%0], %1;" :: "r"(mb), "r"(cnt) : "memory");
}
__device__ __forceinline__ void qk_mbar_expect_tx(uint32_t mb, uint32_t bytes) {
    asm volatile("mbarrier.arrive.expect_tx.shared.b64 _, [%0], %1;"
                 :: "r"(mb), "r"(bytes) : "memory");
}
__device__ __forceinline__ void qk_mbar_wait(uint32_t mb, uint32_t phase) {
    asm volatile(
        "{\n\t.reg .pred P;\n\t"
        "QKW_%=:\n\t"
        "mbarrier.try_wait.parity.acquire.cta.shared::cta.b64 P, [%0], %1, 0x989680;\n\t"
        "@!P bra QKW_%=;\n\t}"
        :: "r"(mb), "r"(phase) : "memory");
}
__device__ __forceinline__ void qk_bulk_g2s(uint32_t dst, const void* src,
                                            uint32_t bytes, uint32_t mb) {
    asm volatile(
        "cp.async.bulk.shared::cluster.global.mbarrier::complete_tx::bytes "
        "[%0], [%1], %2, [%3];"
        :: "r"(dst), "l"(src), "r"(bytes), "r"(mb) : "memory");
}
__device__ __forceinline__ void qk_ldsm_x4(uint32_t& r0, uint32_t& r1,
                                           uint32_t& r2, uint32_t& r3,
                                           uint32_t addr) {
    asm volatile("ldmatrix.sync.aligned.m8n8.x4.shared.b16 {%0,%1,%2,%3}, [%4];"
                 : "=r"(r0), "=r"(r1), "=r"(r2), "=r"(r3) : "r"(addr));
}
__device__ __forceinline__ void qk_mma_s8(int* c, const uint32_t* a,
                                          uint32_t b0, uint32_t b1) {
    asm volatile(
        "mma.sync.aligned.m16n8k32.row.col.s32.s8.s8.s32 "
        "{%0,%1,%2,%3}, {%4,%5,%6,%7}, {%8,%9}, {%0,%1,%2,%3};"
        : "+r"(c[0]), "+r"(c[1]), "+r"(c[2]), "+r"(c[3])
        : "r"(a[0]), "r"(a[1]), "r"(a[2]), "r"(a[3]), "r"(b0), "r"(b1));
}
// chunk swizzle within a 64B row (conflict-free ldmatrix phases)
__device__ __forceinline__ uint32_t qk_sw(int row, int c16) {
    return (uint32_t)(row * 64 + ((c16 ^ ((row >> 1) & 3)) << 4));
}

// ------------------------------------------------------------ prepass kernels
// thread i -> one 16B output chunk: i = (kt*ROWS + r)*4 + c16.
// reads 16 int32 from in[r][kt*64 + c16*16 ..], packs s8 (zp folded for A),
// writes to tiled+swizzled offset ((kt*ROWS + r)*64 + (c16^((r>>1)&3))*16).
__global__ void qk_cvt_a(const int* __restrict__ in, int nchunk) {
    int i = blockIdx.x * blockDim.x + threadIdx.x;
    if (i >= nchunk) return;
    const int c16 = i & 3;
    const int rowg = i >> 2;               // kt*MDIM + m
    const int m = rowg & (MDIM - 1);
    const int kt = rowg >> 12;             // / MDIM
    const int* src = in + (size_t)m * KDIM + kt * 64 + c16 * 16;
    uint32_t pk[4];
#pragma unroll
    for (int j = 0; j < 4; j++) {
        const int4 v = *(const int4*)(src + 4 * j);
        pk[j] =  ((uint32_t)(uint8_t)(v.x - X_ZP))
              | (((uint32_t)(uint8_t)(v.y - X_ZP)) << 8)
              | (((uint32_t)(uint8_t)(v.z - X_ZP)) << 16)
              | (((uint32_t)(uint8_t)(v.w - X_ZP)) << 24);
    }
    const int s = c16 ^ ((m >> 1) & 3);
    *(uint4*)(g_qk_At + (size_t)rowg * 64 + s * 16) =
        make_uint4(pk[0], pk[1], pk[2], pk[3]);
}
__global__ void qk_cvt_b(const int* __restrict__ in, int nchunk) {
    int i = blockIdx.x * blockDim.x + threadIdx.x;
    if (i >= nchunk) return;
    const int c16 = i & 3;
    const int rowg = i >> 2;               // kt*NDIM + n
    const int kt = rowg / NDIM;
    const int n = rowg - kt * NDIM;
    const int* src = in + (size_t)n * KDIM + kt * 64 + c16 * 16;
    uint32_t pk[4];
#pragma unroll
    for (int j = 0; j < 4; j++) {
        const int4 v = *(const int4*)(src + 4 * j);
        pk[j] =  ((uint32_t)(uint8_t)v.x)
              | (((uint32_t)(uint8_t)v.y) << 8)
              | (((uint32_t)(uint8_t)v.z) << 16)
              | (((uint32_t)(uint8_t)v.w) << 24);
    }
    const int s = c16 ^ ((n >> 1) & 3);
    *(uint4*)(g_qk_Bt + (size_t)rowg * 64 + s * 16) =
        make_uint4(pk[0], pk[1], pk[2], pk[3]);
}

// ---------------------------------------------------------------- GEMM kernel
__global__ void __launch_bounds__(256) qk_gemm_i8(
    float* __restrict__ out, const float* __restrict__ bias)
{
    __shared__ __align__(128) int8_t smem[SMEM_TOTAL];
    __shared__ __align__(8) uint64_t mbar[NST];

    const uint32_t sb = qk_smem_u32(smem);
    const uint32_t mb0 = qk_smem_u32(mbar);
    const int tid = threadIdx.x;
    const int wid = tid >> 5;
    const int lid = tid & 31;
    const int wm = wid >> 2;          // 0..1 : 64-row M chunk
    const int wn = wid & 3;           // 0..3 : 32-col N chunk

    const int n0 = blockIdx.x * BN;   // n fastest: B slab L2-resident
    const int m0 = blockIdx.y * BM;

    if (tid == 0)
        for (int s = 0; s < NST; s++) qk_mbar_init(mb0 + 8 * s, 1);
    __syncthreads();

    auto issue = [&](int kt) {        // ONE bulk copy per matrix per stage
        const int s = kt % NST;
        const uint32_t mb = mb0 + 8 * s;
        qk_mbar_expect_tx(mb, STAGE_BYTES);
        qk_bulk_g2s(sb + s * STAGE_BYTES,
                    g_qk_At + ((size_t)kt * MDIM + m0) * 64, A_STAGE_BYTES, mb);
        qk_bulk_g2s(sb + s * STAGE_BYTES + A_STAGE_BYTES,
                    g_qk_Bt + ((size_t)kt * NDIM + n0) * 64, B_STAGE_BYTES, mb);
    };

    int acc[4][4][4];
#pragma unroll
    for (int i = 0; i < 4; i++)
#pragma unroll
        for (int j = 0; j < 4; j++)
#pragma unroll
            for (int e = 0; e < 4; e++) acc[i][j][e] = 0;

    if (tid == 0) { issue(0); issue(1); }

    const int lrow = lid & 15;
    const int lc   = lid >> 4;

    for (int kt = 0; kt < KTILES; kt++) {
        const int sc = kt % NST;
        const uint32_t ph = (uint32_t)(kt / NST) & 1u;

        if (tid == 0 && kt + 2 < KTILES) issue(kt + 2);   // slot freed last iter
        qk_mbar_wait(mb0 + 8 * sc, ph);

        const uint32_t sA = sb + sc * STAGE_BYTES;
        const uint32_t sBB = sA + A_STAGE_BYTES;

#pragma unroll
        for (int kk = 0; kk < 2; kk++) {
            const int c16 = kk * 2 + lc;
            uint32_t a[4][4];
#pragma unroll
            for (int mf = 0; mf < 4; mf++) {
                const int row = wm * 64 + mf * 16 + lrow;
                qk_ldsm_x4(a[mf][0], a[mf][1], a[mf][2], a[mf][3],
                           sA + qk_sw(row, c16));
            }
            uint32_t bq[2][4];
#pragma unroll
            for (int bh = 0; bh < 2; bh++) {
                const int row = wn * 32 + bh * 16 + lrow;
                qk_ldsm_x4(bq[bh][0], bq[bh][1], bq[bh][2], bq[bh][3],
                           sBB + qk_sw(row, c16));
            }
#pragma unroll
            for (int mf = 0; mf < 4; mf++)
#pragma unroll
                for (int nf = 0; nf < 4; nf++) {
                    const int bh = nf >> 1, pr = nf & 1;
                    qk_mma_s8(acc[mf][nf], a[mf], bq[bh][pr], bq[bh][pr + 2]);
                }
        }
        __syncthreads();              // all readers done -> slot reusable
    }

    // -------- epilogue: dequant + bias + requant; FLOAT32 output --------
    const float sxw = SXW_SCALE;
    const int qrow = lid >> 2;
    const int qcol = (lid & 3) * 2;

#pragma unroll
    for (int nf = 0; nf < 4; nf++) {
        const int col = n0 + wn * 32 + nf * 8 + qcol;
        const float b0 = bias[col];
        const float b1 = bias[col + 1];
#pragma unroll
        for (int mf = 0; mf < 4; mf++) {
            const int r0 = m0 + wm * 64 + mf * 16 + qrow;
#pragma unroll
            for (int h = 0; h < 2; h++) {
                const long row = r0 + h * 8;
                float y0 = __fmaf_rn((float)acc[mf][nf][2 * h + 0], sxw, b0);
                float y1 = __fmaf_rn((float)acc[mf][nf][2 * h + 1], sxw, b1);
                float q0 = fminf(fmaxf(rintf(y0), 0.0f), 255.0f);
                float q1 = fminf(fmaxf(rintf(y1), 0.0f), 255.0f);
                float2 v = make_float2(q0, q1);
                *(float2*)(out + row * (long)NDIM + col) = v;
            }
        }
    }
}

// --------------------------------------------------------------------- launch
extern "C" void kernel_launch(void* const* d_in, const int* in_sizes, int n_in,
                              void* d_out, int out_size) {
    (void)in_sizes; (void)n_in; (void)out_size;

    const int*   xq   = (const int*)d_in[0];
    const int*   wq   = (const int*)d_in[1];
    const float* bias = (const float*)d_in[2];

    const int nca = (MDIM * KDIM) / 16;   // 1,048,576
    const int ncb = (NDIM * KDIM) / 16;   // 2,818,048
    qk_cvt_a<<<(nca + 255) / 256, 256>>>(xq, nca);
    qk_cvt_b<<<(ncb + 255) / 256, 256>>>(wq, ncb);

    dim3 grid(NDIM / BN, MDIM / BM);      // (86, 32)
    qk_gemm_i8<<<grid, 256>>>((float*)d_out, bias);
}